// round 5
// baseline (speedup 1.0000x reference)
#include <cuda_runtime.h>
#include <cstdint>

// ---------------------------------------------------------------------------
// HybridSigLSTM: rolling signature + 2-layer LSTM(H=50) + MLP head + pd clip
// B=4096, S=256, DIN=4, WIN=5, D_AUG=5, SIG=30, COMB=35, GATES=4*50=200
// ---------------------------------------------------------------------------

#define B_TOT 4096
#define S_LEN 256
#define GATES 200
#define BT    28      // batch elements per CTA in recurrent kernel
#define NT    512     // threads in recurrent kernel

typedef unsigned long long u64;

// scratch (device globals: allocation-free rule)
__device__ float g_xfeat[(size_t)B_TOT * S_LEN * 36];   // [b*S+t][36] padded sig feats
__device__ float g_pre0 [(size_t)B_TOT * S_LEN * 200];  // [t][b][o] transposed

// ---------------- helpers ----------------
__device__ __forceinline__ u64 ffma2(u64 a, u64 b, u64 c) {
    u64 d;
    asm("fma.rn.f32x2 %0, %1, %2, %3;" : "=l"(d) : "l"(a), "l"(b), "l"(c));
    return d;
}
__device__ __forceinline__ u64 pack2(float a, float b) {
    u64 r;
    asm("mov.b64 %0, {%1, %2};" : "=l"(r) : "f"(a), "f"(b));
    return r;
}
__device__ __forceinline__ float2 unpack2(u64 v) {
    float2 f;
    asm("mov.b64 {%0, %1}, %2;" : "=f"(f.x), "=f"(f.y) : "l"(v));
    return f;
}
__device__ __forceinline__ float ex2f(float x) {
    float y; asm("ex2.approx.f32 %0, %1;" : "=f"(y) : "f"(x)); return y;
}
__device__ __forceinline__ float rcpf(float x) {
    float y; asm("rcp.approx.f32 %0, %1;" : "=f"(y) : "f"(x)); return y;
}
__device__ __forceinline__ float sigf(float x) {
    return rcpf(1.0f + ex2f(-1.4426950408889634f * x));
}
__device__ __forceinline__ float tanha(float x) {
    return 2.0f * rcpf(1.0f + ex2f(-2.8853900817779268f * x)) - 1.0f;
}
__device__ __forceinline__ void cpasync16(uint32_t saddr, const void* gptr) {
    asm volatile("cp.async.cg.shared.global [%0], [%1], 16;" :: "r"(saddr), "l"(gptr));
}
__device__ __forceinline__ void cpcommit() {
    asm volatile("cp.async.commit_group;" ::: "memory");
}
__device__ __forceinline__ void cpwait0() {
    asm volatile("cp.async.wait_group 0;" ::: "memory");
}

// profiling pad (shifts ncu capture slot onto rec_kernel)
__global__ void pad_kernel() {}

// ---------------------------------------------------------------------------
// K1: rolling signature features -> g_xfeat[b*S+t][0:36]
// ---------------------------------------------------------------------------
__global__ __launch_bounds__(256) void sig_kernel(const float* __restrict__ features) {
    int gid = blockIdx.x * 256 + threadIdx.x;      // gid = b*S + t
    int b = gid >> 8;
    int t = gid & 255;
    const float4* f4 = (const float4*)features + (size_t)b * S_LEN;

    float a[5][5];   // window of time-augmented path [k][dim]
#pragma unroll
    for (int k = 0; k < 5; k++) {
        int idx = t + k - 4; if (idx < 0) idx = 0;
        float4 fv = __ldg(&f4[idx]);
        a[k][0] = (float)idx * (1.0f / 255.0f);
        a[k][1] = fv.x; a[k][2] = fv.y; a[k][3] = fv.z; a[k][4] = fv.w;
    }
    float x[36];
    x[0] = a[4][1]; x[1] = a[4][2]; x[2] = a[4][3]; x[3] = a[4][4];
#pragma unroll
    for (int i = 0; i < 5; i++) x[4 + i] = a[4][i] - a[0][i];
#pragma unroll
    for (int i = 0; i < 5; i++) {
#pragma unroll
        for (int j = 0; j < 5; j++) {
            float s = 0.0f;
#pragma unroll
            for (int k = 0; k < 4; k++) s += (a[k + 1][i] - a[k][i]) * a[k][j];
            x[9 + i * 5 + j] = s;
        }
    }
    x[34] = 0.0f; x[35] = 0.0f;

    float4* dst = (float4*)(g_xfeat + (size_t)gid * 36);
#pragma unroll
    for (int q = 0; q < 9; q++)
        dst[q] = make_float4(x[4 * q], x[4 * q + 1], x[4 * q + 2], x[4 * q + 3]);
}

// ---------------------------------------------------------------------------
// K2: pre0[t][b][o] = b_ih0[o]+b_hh0[o] + sum_{k<34} W_ih0[o][k]*x[b,t,k]
// ---------------------------------------------------------------------------
__global__ __launch_bounds__(256) void pre0_kernel(const float* __restrict__ w_ih0,
                                                   const float* __restrict__ b_ih0,
                                                   const float* __restrict__ b_hh0) {
    __shared__ __align__(16) float xs[64][36];
    int tid = threadIdx.x;
    size_t row0 = (size_t)blockIdx.x * 64;

    u64 wp[17];
    float bias = 0.0f;
    if (tid < GATES) {
        const float* wr = w_ih0 + tid * 35;
#pragma unroll
        for (int j = 0; j < 17; j++) wp[j] = pack2(wr[2 * j], wr[2 * j + 1]);
        bias = b_ih0[tid] + b_hh0[tid];
    }
    const float* src = g_xfeat + row0 * 36;
#pragma unroll
    for (int n = 0; n < 9; n++) ((float*)xs)[tid + n * 256] = src[tid + n * 256];
    __syncthreads();

    if (tid < GATES) {
        for (int r = 0; r < 64; r += 2) {
            const ulonglong2* xA = (const ulonglong2*)&xs[r][0];
            const ulonglong2* xB = (const ulonglong2*)&xs[r + 1][0];
            u64 aA = 0ull, aB = 0ull;
#pragma unroll
            for (int q = 0; q < 8; q++) {
                ulonglong2 vA = xA[q], vB = xB[q];
                aA = ffma2(wp[2 * q],     vA.x, aA);
                aB = ffma2(wp[2 * q],     vB.x, aB);
                aA = ffma2(wp[2 * q + 1], vA.y, aA);
                aB = ffma2(wp[2 * q + 1], vB.y, aB);
            }
            u64 tA = ((const u64*)&xs[r][0])[16];
            u64 tB = ((const u64*)&xs[r + 1][0])[16];
            aA = ffma2(wp[16], tA, aA);
            aB = ffma2(wp[16], tB, aB);
            float2 fA = unpack2(aA), fB = unpack2(aB);
            size_t ra = row0 + r, rb = row0 + r + 1;    // row = b*S + t
            size_t ia = ((ra & 255) * (size_t)B_TOT + (ra >> 8)) * 200 + tid;
            size_t ib = ((rb & 255) * (size_t)B_TOT + (rb >> 8)) * 200 + tid;
            g_pre0[ia] = fA.x + fA.y + bias;
            g_pre0[ib] = fB.x + fB.y + bias;
        }
    }
}

// ---------------------------------------------------------------------------
// K3: recurrent kernel. One CTA = BT batch elements, 256 steps, 512 threads.
// Gate row o split across thread pair (2o, 2o+1): half 0 = h[0:26),
// half 1 = h[26:52) (floats 50,51 zero pads). Partials combined with one
// shfl.down per accumulator.
// ---------------------------------------------------------------------------
__global__ __launch_bounds__(NT, 1) void rec_kernel(
    const float* __restrict__ w_ih0, const float* __restrict__ w_hh0,
    const float* __restrict__ w_ih1, const float* __restrict__ w_hh1,
    const float* __restrict__ b_ih1, const float* __restrict__ b_hh1,
    const float* __restrict__ w1,    const float* __restrict__ b1,
    const float* __restrict__ w2,    const float* __restrict__ b2,
    float* __restrict__ out)
{
    __shared__ __align__(16) float zbuf[BT * 200];   // pre0 tile, then z0, then z1
    __shared__ __align__(16) float h0s[BT][52];
    __shared__ __align__(16) float h1s[BT][52];
    __shared__ __align__(16) float w1s[25][52];
    __shared__ float hd[BT][25];
    __shared__ float pd_s[BT];
    __shared__ float b1s[25], w2s[25];
    __shared__ float b2s;

    const int tid = threadIdx.x;
    const int b0  = blockIdx.x * BT;
    int bt = B_TOT - b0; if (bt > BT) bt = BT;       // 28 or 8 (even)

    const int o    = tid >> 1;        // gate row (valid for tid<400)
    const int half = tid & 1;
    const unsigned shmask = (tid >= 384) ? 0x0000FFFFu : 0xFFFFFFFFu;

    // --- per-thread half-row weights, packed f32x2 (13 u64 each) ---
    u64 w0p[13], wi1p[13], wh1p[13];
    float wpd = 0.0f, bias1 = 0.0f;
    if (tid < 2 * GATES) {
        const float* r0 = w_hh0 + o * 50 + half * 26;
        const float* r1 = w_ih1 + o * 50 + half * 26;
        const float* r2 = w_hh1 + o * 50 + half * 26;
#pragma unroll
        for (int j = 0; j < 13; j++) {
            bool pad = (half == 1 && j == 12);   // floats 50,51 of the row
            w0p[j]  = pad ? 0ull : pack2(r0[2 * j], r0[2 * j + 1]);
            wi1p[j] = pad ? 0ull : pack2(r1[2 * j], r1[2 * j + 1]);
            wh1p[j] = pad ? 0ull : pack2(r2[2 * j], r2[2 * j + 1]);
        }
        wpd   = w_ih0[o * 35 + 34];
        bias1 = b_ih1[o] + b_hh1[o];
    }

    // --- init state / head weights ---
    for (int i = tid; i < BT * 52; i += NT) { ((float*)h0s)[i] = 0.0f; ((float*)h1s)[i] = 0.0f; }
    for (int i = tid; i < 25 * 52; i += NT) ((float*)w1s)[i] = 0.0f;
    __syncthreads();   // zero w1s before scattered fill
    for (int i = tid; i < 1250; i += NT) { int j = i / 50, k = i - j * 50; w1s[j][k] = w1[i]; }
    if (tid < 25) { b1s[tid] = b1[tid]; w2s[tid] = w2[tid]; }
    if (tid < BT) pd_s[tid] = 0.0f;
    if (tid == 0) b2s = b2[0];
    float c0r[3], c1r[3];
#pragma unroll
    for (int n = 0; n < 3; n++) { c0r[n] = 0.0f; c1r[n] = 0.0f; }

    const int nact = bt * 50;
    const int nhd  = bt * 25;
    const int nz4  = bt * 50;   // float4 count of pre0 tile
    const uint32_t zsm = (uint32_t)__cvta_generic_to_shared(zbuf);

    // prologue: fetch pre0 tile for t=0
    {
        const float4* psrc = (const float4*)(g_pre0 + (size_t)b0 * 200);
#pragma unroll
        for (int n = 0; n < 3; n++) {
            int idx = tid + n * NT;
            if (idx < nz4) cpasync16(zsm + idx * 16, psrc + idx);
        }
        cpcommit();
        cpwait0();
    }
    __syncthreads();

    for (int t = 0; t < S_LEN; t++) {
        // --- Z0: z = pre0 + W_hh0[o,:]·h0[b,:] + wpd*pd[b] ---
        if (tid < 2 * GATES) {
            for (int b = 0; b < bt; b += 2) {
                const u64* hA = (const u64*)&h0s[b][0] + half * 13;
                const u64* hB = (const u64*)&h0s[b + 1][0] + half * 13;
                u64 aA = 0ull, aB = 0ull;
#pragma unroll
                for (int j = 0; j < 13; j++) {
                    aA = ffma2(w0p[j], hA[j], aA);
                    aB = ffma2(w0p[j], hB[j], aB);
                }
                float2 fA = unpack2(aA), fB = unpack2(aB);
                float sA = fA.x + fA.y, sB = fB.x + fB.y;
                float oA = __shfl_down_sync(shmask, sA, 1);
                float oB = __shfl_down_sync(shmask, sB, 1);
                if (half == 0) {
                    float pA = zbuf[b * 200 + o];
                    float pB = zbuf[(b + 1) * 200 + o];
                    zbuf[b * 200 + o]       = pA + sA + oA + wpd * pd_s[b];
                    zbuf[(b + 1) * 200 + o] = pB + sB + oB + wpd * pd_s[b + 1];
                }
            }
        }
        __syncthreads();

        // --- act0: LSTM cell layer 0 ---
#pragma unroll
        for (int n = 0; n < 3; n++) {
            int idx = tid + n * NT;
            if (idx < nact) {
                int b = idx / 50, u = idx - b * 50;
                const float* zr = zbuf + b * 200;
                float iv = zr[u], fv = zr[u + 50], gv = zr[u + 100], ov = zr[u + 150];
                float c = sigf(fv) * c0r[n] + sigf(iv) * tanha(gv);
                c0r[n] = c;
                h0s[b][u] = sigf(ov) * tanha(c);
            }
        }
        __syncthreads();

        // --- Z1: z = bias1 + W_ih1[o,:]·h0new[b,:] + W_hh1[o,:]·h1[b,:] ---
        if (tid < 2 * GATES) {
            for (int b = 0; b < bt; b += 2) {
                const u64* hA0 = (const u64*)&h0s[b][0] + half * 13;
                const u64* hB0 = (const u64*)&h0s[b + 1][0] + half * 13;
                const u64* hA1 = (const u64*)&h1s[b][0] + half * 13;
                const u64* hB1 = (const u64*)&h1s[b + 1][0] + half * 13;
                u64 aA = 0ull, aB = 0ull;
#pragma unroll
                for (int j = 0; j < 13; j++) {
                    aA = ffma2(wi1p[j], hA0[j], aA);
                    aB = ffma2(wi1p[j], hB0[j], aB);
                    aA = ffma2(wh1p[j], hA1[j], aA);
                    aB = ffma2(wh1p[j], hB1[j], aB);
                }
                float2 fA = unpack2(aA), fB = unpack2(aB);
                float sA = fA.x + fA.y, sB = fB.x + fB.y;
                float oA = __shfl_down_sync(shmask, sA, 1);
                float oB = __shfl_down_sync(shmask, sB, 1);
                if (half == 0) {
                    zbuf[b * 200 + o]       = bias1 + sA + oA;
                    zbuf[(b + 1) * 200 + o] = bias1 + sB + oB;
                }
            }
        }
        __syncthreads();

        // --- act1: LSTM cell layer 1 ---
#pragma unroll
        for (int n = 0; n < 3; n++) {
            int idx = tid + n * NT;
            if (idx < nact) {
                int b = idx / 50, u = idx - b * 50;
                const float* zr = zbuf + b * 200;
                float iv = zr[u], fv = zr[u + 50], gv = zr[u + 100], ov = zr[u + 150];
                float c = sigf(fv) * c1r[n] + sigf(iv) * tanha(gv);
                c1r[n] = c;
                h1s[b][u] = sigf(ov) * tanha(c);
            }
        }
        __syncthreads();

        // zbuf now free: prefetch next step's pre0 tile under the head phases
        if (t + 1 < S_LEN) {
            const float4* psrc = (const float4*)(g_pre0 + ((size_t)(t + 1) * B_TOT + b0) * 200);
#pragma unroll
            for (int n = 0; n < 3; n++) {
                int idx = tid + n * NT;
                if (idx < nz4) cpasync16(zsm + idx * 16, psrc + idx);
            }
        }
        cpcommit();

        // --- head layer 1: hd = relu(W1·h1 + b1), packed f32x2 over 50 floats ---
#pragma unroll
        for (int n = 0; n < 2; n++) {
            int idx = tid + n * NT;
            if (idx < nhd) {
                int b = idx / 25, j = idx - b * 25;
                const u64* wv = (const u64*)&w1s[j][0];
                const u64* hv = (const u64*)&h1s[b][0];
                u64 acc = 0ull;
#pragma unroll
                for (int q = 0; q < 25; q++) acc = ffma2(wv[q], hv[q], acc);  // 25 u64 = 50 floats
                float2 f = unpack2(acc);
                hd[b][j] = fmaxf(f.x + f.y + b1s[j], 0.0f);
            }
        }
        __syncthreads();

        // --- head layer 2 + pd update ---
        if (tid < bt) {
            float s = b2s;
#pragma unroll
            for (int j = 0; j < 25; j++) s += w2s[j] * hd[tid][j];
            float nd = pd_s[tid] + 0.2f * tanha(s);
            nd = fminf(fmaxf(nd, -1.5f), 1.5f);
            pd_s[tid] = nd;
            out[(size_t)(b0 + tid) * S_LEN + t] = nd;
        }
        cpwait0();
        __syncthreads();
    }
}

// ---------------------------------------------------------------------------
extern "C" void kernel_launch(void* const* d_in, const int* in_sizes, int n_in,
                              void* d_out, int out_size) {
    const float* features = (const float*)d_in[0];
    const float* w_ih0    = (const float*)d_in[1];
    const float* w_hh0    = (const float*)d_in[2];
    const float* b_ih0    = (const float*)d_in[3];
    const float* b_hh0    = (const float*)d_in[4];
    const float* w_ih1    = (const float*)d_in[5];
    const float* w_hh1    = (const float*)d_in[6];
    const float* b_ih1    = (const float*)d_in[7];
    const float* b_hh1    = (const float*)d_in[8];
    const float* w1       = (const float*)d_in[9];
    const float* b1       = (const float*)d_in[10];
    const float* w2       = (const float*)d_in[11];
    const float* b2       = (const float*)d_in[12];
    float* out = (float*)d_out;

    // pad launches: shift ncu's captured slot (global launch idx 6) onto rec_kernel
    pad_kernel<<<1, 32>>>();
    pad_kernel<<<1, 32>>>();
    pad_kernel<<<1, 32>>>();
    pad_kernel<<<1, 32>>>();
    sig_kernel<<<(B_TOT * S_LEN) / 256, 256>>>(features);
    pre0_kernel<<<(B_TOT * S_LEN) / 64, 256>>>(w_ih0, b_ih0, b_hh0);
    rec_kernel<<<(B_TOT + BT - 1) / BT, NT>>>(w_ih0, w_hh0, w_ih1, w_hh1,
                                              b_ih1, b_hh1, w1, b1, w2, b2, out);
}

// round 6
// speedup vs baseline: 1.1013x; 1.1013x over previous
#include <cuda_runtime.h>
#include <cstdint>

// ---------------------------------------------------------------------------
// HybridSigLSTM: rolling signature + 2-layer LSTM(H=50) + MLP head + pd clip
// B=4096, S=256, DIN=4, WIN=5, D_AUG=5, SIG=30, COMB=35, GATES=4*50=200
// ---------------------------------------------------------------------------

#define B_TOT 4096
#define S_LEN 256
#define GATES 200
#define BT    28      // batch elements per CTA in recurrent kernel
#define NT    256     // threads in recurrent kernel

typedef unsigned long long u64;

// scratch (device global: allocation-free rule)
__device__ float g_pre0[(size_t)B_TOT * S_LEN * 200];  // [t][b][o]

// ---------------- helpers ----------------
__device__ __forceinline__ u64 ffma2(u64 a, u64 b, u64 c) {
    u64 d;
    asm("fma.rn.f32x2 %0, %1, %2, %3;" : "=l"(d) : "l"(a), "l"(b), "l"(c));
    return d;
}
__device__ __forceinline__ u64 pack2(float a, float b) {
    u64 r;
    asm("mov.b64 %0, {%1, %2};" : "=l"(r) : "f"(a), "f"(b));
    return r;
}
__device__ __forceinline__ float2 unpack2(u64 v) {
    float2 f;
    asm("mov.b64 {%0, %1}, %2;" : "=f"(f.x), "=f"(f.y) : "l"(v));
    return f;
}
__device__ __forceinline__ float ex2f(float x) {
    float y; asm("ex2.approx.f32 %0, %1;" : "=f"(y) : "f"(x)); return y;
}
__device__ __forceinline__ float rcpf(float x) {
    float y; asm("rcp.approx.f32 %0, %1;" : "=f"(y) : "f"(x)); return y;
}
__device__ __forceinline__ float sigf(float x) {
    return rcpf(1.0f + ex2f(-1.4426950408889634f * x));
}
__device__ __forceinline__ float tanha(float x) {
    return 2.0f * rcpf(1.0f + ex2f(-2.8853900817779268f * x)) - 1.0f;
}
__device__ __forceinline__ void cpasync16(uint32_t saddr, const void* gptr) {
    asm volatile("cp.async.cg.shared.global [%0], [%1], 16;" :: "r"(saddr), "l"(gptr));
}
__device__ __forceinline__ void cpcommit() {
    asm volatile("cp.async.commit_group;" ::: "memory");
}
__device__ __forceinline__ void cpwait0() {
    asm volatile("cp.async.wait_group 0;" ::: "memory");
}

// ---------------------------------------------------------------------------
// K1: fused signature + input projection.
// CTA = 64 consecutive timesteps of one batch b. Computes sig features in
// SMEM, then pre0[t][b][o] = b_ih0[o]+b_hh0[o] + sum_{k<34} W_ih0[o][k]*x[k].
// ---------------------------------------------------------------------------
__global__ __launch_bounds__(256) void pre0f_kernel(const float* __restrict__ features,
                                                    const float* __restrict__ w_ih0,
                                                    const float* __restrict__ b_ih0,
                                                    const float* __restrict__ b_hh0) {
    __shared__ __align__(16) float4 sf[68];        // raw feature window
    __shared__ __align__(16) float xs[64][36];
    const int tid = threadIdx.x;
    const int b   = blockIdx.x >> 2;
    const int t0  = (blockIdx.x & 3) << 6;

    // load feature window rows t0-4 .. t0+63 (clamped)
    if (tid < 68) {
        int gi = t0 - 4 + tid; if (gi < 0) gi = 0;
        sf[tid] = __ldg((const float4*)features + (size_t)b * S_LEN + gi);
    }

    // weights per gate row
    u64 wp[17];
    float bias = 0.0f;
    if (tid < GATES) {
        const float* wr = w_ih0 + tid * 35;
#pragma unroll
        for (int j = 0; j < 17; j++) wp[j] = pack2(wr[2 * j], wr[2 * j + 1]);
        bias = b_ih0[tid] + b_hh0[tid];
    }
    __syncthreads();

    // compute sig features for own row
    if (tid < 64) {
        const int t = t0 + tid;
        float a[5][5];
#pragma unroll
        for (int k = 0; k < 5; k++) {
            int gi = t + k - 4;
            int idx = gi < 0 ? 0 : gi;
            float4 fv = sf[tid + k];            // == features[b][clamp(gi,0)]
            a[k][0] = (float)idx * (1.0f / 255.0f);
            a[k][1] = fv.x; a[k][2] = fv.y; a[k][3] = fv.z; a[k][4] = fv.w;
        }
        float* x = xs[tid];
        x[0] = a[4][1]; x[1] = a[4][2]; x[2] = a[4][3]; x[3] = a[4][4];
#pragma unroll
        for (int i = 0; i < 5; i++) x[4 + i] = a[4][i] - a[0][i];
#pragma unroll
        for (int i = 0; i < 5; i++) {
#pragma unroll
            for (int j = 0; j < 5; j++) {
                float s = 0.0f;
#pragma unroll
                for (int k = 0; k < 4; k++) s += (a[k + 1][i] - a[k][i]) * a[k][j];
                x[9 + i * 5 + j] = s;
            }
        }
        x[34] = 0.0f; x[35] = 0.0f;
    }
    __syncthreads();

    if (tid < GATES) {
        const size_t row0 = (size_t)b * S_LEN + t0;
        for (int r = 0; r < 64; r += 2) {
            const ulonglong2* xA = (const ulonglong2*)&xs[r][0];
            const ulonglong2* xB = (const ulonglong2*)&xs[r + 1][0];
            u64 aA = 0ull, aB = 0ull;
#pragma unroll
            for (int q = 0; q < 8; q++) {
                ulonglong2 vA = xA[q], vB = xB[q];
                aA = ffma2(wp[2 * q],     vA.x, aA);
                aB = ffma2(wp[2 * q],     vB.x, aB);
                aA = ffma2(wp[2 * q + 1], vA.y, aA);
                aB = ffma2(wp[2 * q + 1], vB.y, aB);
            }
            u64 tA = ((const u64*)&xs[r][0])[16];
            u64 tB = ((const u64*)&xs[r + 1][0])[16];
            aA = ffma2(wp[16], tA, aA);
            aB = ffma2(wp[16], tB, aB);
            float2 fA = unpack2(aA), fB = unpack2(aB);
            size_t ra = row0 + r, rb = row0 + r + 1;     // row = b*S + t
            size_t ia = ((ra & 255) * (size_t)B_TOT + (ra >> 8)) * 200 + tid;
            size_t ib = ((rb & 255) * (size_t)B_TOT + (rb >> 8)) * 200 + tid;
            g_pre0[ia] = fA.x + fA.y + bias;
            g_pre0[ib] = fB.x + fB.y + bias;
        }
    }
}

// ---------------------------------------------------------------------------
// K2: recurrent kernel. One CTA = BT batches, 256 steps, 256 threads.
// Thread o<200 owns full gate rows (26 u64 each, zero-padded) of
// W_hh0 / W_ih1 / W_hh1 in registers. 4-way batch unroll. pre0 tile lives
// in a ping-pong SMEM buffer prefetched by warp 7 via cp.async; Z phases
// update it in place. Head = warp-per-batch with shfl reduce.
// ---------------------------------------------------------------------------
// dynamic SMEM layout (floats):
//   P0    @ 0      : 5600  (BT*200)
//   P1    @ 5600   : 5600
//   h0s   @ 11200  : 1456  (BT*52)
//   h1s   @ 12656  : 1456
//   w1s   @ 14112  : 1300  (25*52)
//   pd_s  @ 15412  : 28
//   b1s   @ 15440  : 25
//   w2s   @ 15465  : 25
//   b2s   @ 15490  : 1
#define SM_FLOATS 15491

__global__ __launch_bounds__(NT, 1) void rec_kernel(
    const float* __restrict__ w_ih0, const float* __restrict__ w_hh0,
    const float* __restrict__ w_ih1, const float* __restrict__ w_hh1,
    const float* __restrict__ b_ih1, const float* __restrict__ b_hh1,
    const float* __restrict__ w1,    const float* __restrict__ b1,
    const float* __restrict__ w2,    const float* __restrict__ b2,
    float* __restrict__ out)
{
    extern __shared__ __align__(16) float sm[];
    float* Pbuf[2] = { sm, sm + 5600 };
    float* h0s  = sm + 11200;
    float* h1s  = sm + 12656;
    float* w1s  = sm + 14112;
    float* pd_s = sm + 15412;
    float* b1s  = sm + 15440;
    float* w2s  = sm + 15465;
    float* b2sp = sm + 15490;

    const int tid = threadIdx.x;
    const int wid = tid >> 5;
    const int lane = tid & 31;
    const int b0  = blockIdx.x * BT;
    int bt = B_TOT - b0; if (bt > BT) bt = BT;     // 28 or 8 (mult of 4)

    // --- register-resident weight rows, padded to 26 u64 (52 floats) ---
    u64 w0p[26], wi1p[26], wh1p[26];
    float wpd = 0.0f, bias1 = 0.0f;
    if (tid < GATES) {
        const float* r0 = w_hh0 + tid * 50;
        const float* r1 = w_ih1 + tid * 50;
        const float* r2 = w_hh1 + tid * 50;
#pragma unroll
        for (int q = 0; q < 25; q++) {
            w0p[q]  = pack2(r0[2 * q], r0[2 * q + 1]);
            wi1p[q] = pack2(r1[2 * q], r1[2 * q + 1]);
            wh1p[q] = pack2(r2[2 * q], r2[2 * q + 1]);
        }
        w0p[25] = 0ull; wi1p[25] = 0ull; wh1p[25] = 0ull;
        wpd   = w_ih0[tid * 35 + 34];
        bias1 = b_ih1[tid] + b_hh1[tid];
    }

    // --- init state / head weights (no extra barrier needed: disjoint) ---
    for (int i = tid; i < BT * 52; i += NT) { h0s[i] = 0.0f; h1s[i] = 0.0f; }
    for (int i = tid; i < 1300; i += NT) {
        int j = i / 52, k = i - j * 52;
        w1s[i] = (k < 50) ? w1[j * 50 + k] : 0.0f;
    }
    if (tid < 25) { b1s[tid] = b1[tid]; w2s[tid] = w2[tid]; }
    if (tid < BT) pd_s[tid] = 0.0f;
    if (tid == 0) b2sp[0] = b2[0];
    float c0r[6], c1r[6];
#pragma unroll
    for (int n = 0; n < 6; n++) { c0r[n] = 0.0f; c1r[n] = 0.0f; }

    const int nact = bt * 50;
    const int nz4  = bt * 50;    // float4 count of one pre0 tile
    const uint32_t sm0 = (uint32_t)__cvta_generic_to_shared(Pbuf[0]);
    const uint32_t sm1 = (uint32_t)__cvta_generic_to_shared(Pbuf[1]);

    // prologue: fill P0 with pre0(t=0)
    {
        const float4* psrc = (const float4*)(g_pre0 + (size_t)b0 * 200);
        for (int idx = tid; idx < nz4; idx += NT)
            cpasync16(sm0 + idx * 16, psrc + idx);
        cpcommit(); cpwait0();
    }
    __syncthreads();

    for (int t = 0; t < S_LEN; t++) {
        float* cur = Pbuf[t & 1];
        const uint32_t nxtsm = (t & 1) ? sm0 : sm1;

        // --- Z0 (threads<200)  ||  warp 7 prefetches pre0(t+1) into nxt ---
        if (tid < GATES) {
            const int o = tid;
            for (int b = 0; b < bt; b += 4) {
                const ulonglong2* hA = (const ulonglong2*)(h0s + (b + 0) * 52);
                const ulonglong2* hB = (const ulonglong2*)(h0s + (b + 1) * 52);
                const ulonglong2* hC = (const ulonglong2*)(h0s + (b + 2) * 52);
                const ulonglong2* hD = (const ulonglong2*)(h0s + (b + 3) * 52);
                u64 aA = 0ull, aB = 0ull, aC = 0ull, aD = 0ull;
#pragma unroll
                for (int j = 0; j < 13; j++) {
                    ulonglong2 vA = hA[j], vB = hB[j], vC = hC[j], vD = hD[j];
                    aA = ffma2(w0p[2 * j], vA.x, aA); aA = ffma2(w0p[2 * j + 1], vA.y, aA);
                    aB = ffma2(w0p[2 * j], vB.x, aB); aB = ffma2(w0p[2 * j + 1], vB.y, aB);
                    aC = ffma2(w0p[2 * j], vC.x, aC); aC = ffma2(w0p[2 * j + 1], vC.y, aC);
                    aD = ffma2(w0p[2 * j], vD.x, aD); aD = ffma2(w0p[2 * j + 1], vD.y, aD);
                }
                float2 fA = unpack2(aA), fB = unpack2(aB), fC = unpack2(aC), fD = unpack2(aD);
                cur[(b + 0) * 200 + o] += fA.x + fA.y + wpd * pd_s[b + 0];
                cur[(b + 1) * 200 + o] += fB.x + fB.y + wpd * pd_s[b + 1];
                cur[(b + 2) * 200 + o] += fC.x + fC.y + wpd * pd_s[b + 2];
                cur[(b + 3) * 200 + o] += fD.x + fD.y + wpd * pd_s[b + 3];
            }
        } else if (wid == 7 && t + 1 < S_LEN) {
            const float4* psrc = (const float4*)(g_pre0 + ((size_t)(t + 1) * B_TOT + b0) * 200);
            for (int idx = lane; idx < nz4; idx += 32)
                cpasync16(nxtsm + idx * 16, psrc + idx);
            cpcommit();
        }
        __syncthreads();

        // --- act0 ---
#pragma unroll
        for (int n = 0; n < 6; n++) {
            int idx = tid + n * NT;
            if (idx < nact) {
                int b = idx / 50, u = idx - b * 50;
                const float* zr = cur + b * 200;
                float iv = zr[u], fv = zr[u + 50], gv = zr[u + 100], ov = zr[u + 150];
                float c = sigf(fv) * c0r[n] + sigf(iv) * tanha(gv);
                c0r[n] = c;
                h0s[b * 52 + u] = sigf(ov) * tanha(c);
            }
        }
        __syncthreads();

        // --- Z1 ---
        if (tid < GATES) {
            const int o = tid;
            for (int b = 0; b < bt; b += 4) {
                const ulonglong2* gA = (const ulonglong2*)(h0s + (b + 0) * 52);
                const ulonglong2* gB = (const ulonglong2*)(h0s + (b + 1) * 52);
                const ulonglong2* gC = (const ulonglong2*)(h0s + (b + 2) * 52);
                const ulonglong2* gD = (const ulonglong2*)(h0s + (b + 3) * 52);
                const ulonglong2* kA = (const ulonglong2*)(h1s + (b + 0) * 52);
                const ulonglong2* kB = (const ulonglong2*)(h1s + (b + 1) * 52);
                const ulonglong2* kC = (const ulonglong2*)(h1s + (b + 2) * 52);
                const ulonglong2* kD = (const ulonglong2*)(h1s + (b + 3) * 52);
                u64 aA = 0ull, aB = 0ull, aC = 0ull, aD = 0ull;
#pragma unroll
                for (int j = 0; j < 13; j++) {
                    ulonglong2 vA = gA[j], vB = gB[j], vC = gC[j], vD = gD[j];
                    aA = ffma2(wi1p[2 * j], vA.x, aA); aA = ffma2(wi1p[2 * j + 1], vA.y, aA);
                    aB = ffma2(wi1p[2 * j], vB.x, aB); aB = ffma2(wi1p[2 * j + 1], vB.y, aB);
                    aC = ffma2(wi1p[2 * j], vC.x, aC); aC = ffma2(wi1p[2 * j + 1], vC.y, aC);
                    aD = ffma2(wi1p[2 * j], vD.x, aD); aD = ffma2(wi1p[2 * j + 1], vD.y, aD);
                    ulonglong2 uA = kA[j], uB = kB[j], uC = kC[j], uD = kD[j];
                    aA = ffma2(wh1p[2 * j], uA.x, aA); aA = ffma2(wh1p[2 * j + 1], uA.y, aA);
                    aB = ffma2(wh1p[2 * j], uB.x, aB); aB = ffma2(wh1p[2 * j + 1], uB.y, aB);
                    aC = ffma2(wh1p[2 * j], uC.x, aC); aC = ffma2(wh1p[2 * j + 1], uC.y, aC);
                    aD = ffma2(wh1p[2 * j], uD.x, aD); aD = ffma2(wh1p[2 * j + 1], uD.y, aD);
                }
                float2 fA = unpack2(aA), fB = unpack2(aB), fC = unpack2(aC), fD = unpack2(aD);
                cur[(b + 0) * 200 + o] = bias1 + fA.x + fA.y;
                cur[(b + 1) * 200 + o] = bias1 + fB.x + fB.y;
                cur[(b + 2) * 200 + o] = bias1 + fC.x + fC.y;
                cur[(b + 3) * 200 + o] = bias1 + fD.x + fD.y;
            }
        }
        __syncthreads();

        // --- act1 ---
#pragma unroll
        for (int n = 0; n < 6; n++) {
            int idx = tid + n * NT;
            if (idx < nact) {
                int b = idx / 50, u = idx - b * 50;
                const float* zr = cur + b * 200;
                float iv = zr[u], fv = zr[u + 50], gv = zr[u + 100], ov = zr[u + 150];
                float c = sigf(fv) * c1r[n] + sigf(iv) * tanha(gv);
                c1r[n] = c;
                h1s[b * 52 + u] = sigf(ov) * tanha(c);
            }
        }
        __syncthreads();

        // --- head: warp-per-batch, lanes 0-24 = hidden units, shfl reduce ---
        for (int b = wid; b < bt; b += 8) {
            float v = 0.0f;
            if (lane < 25) {
                const u64* wv = (const u64*)(w1s + lane * 52);
                const u64* hv = (const u64*)(h1s + b * 52);
                u64 acc = 0ull;
#pragma unroll
                for (int q = 0; q < 26; q++) acc = ffma2(wv[q], hv[q], acc);
                float2 f = unpack2(acc);
                v = w2s[lane] * fmaxf(f.x + f.y + b1s[lane], 0.0f);
            }
#pragma unroll
            for (int k = 16; k > 0; k >>= 1) v += __shfl_xor_sync(0xFFFFFFFFu, v, k);
            if (lane == 0) {
                float nd = pd_s[b] + 0.2f * tanha(v + b2sp[0]);
                nd = fminf(fmaxf(nd, -1.5f), 1.5f);
                pd_s[b] = nd;
                out[(size_t)(b0 + b) * S_LEN + t] = nd;
            }
        }
        if (wid == 7) cpwait0();   // prefetch must land before next step
        __syncthreads();
    }
}

// ---------------------------------------------------------------------------
extern "C" void kernel_launch(void* const* d_in, const int* in_sizes, int n_in,
                              void* d_out, int out_size) {
    const float* features = (const float*)d_in[0];
    const float* w_ih0    = (const float*)d_in[1];
    const float* w_hh0    = (const float*)d_in[2];
    const float* b_ih0    = (const float*)d_in[3];
    const float* b_hh0    = (const float*)d_in[4];
    const float* w_ih1    = (const float*)d_in[5];
    const float* w_hh1    = (const float*)d_in[6];
    const float* b_ih1    = (const float*)d_in[7];
    const float* b_hh1    = (const float*)d_in[8];
    const float* w1       = (const float*)d_in[9];
    const float* b1       = (const float*)d_in[10];
    const float* w2       = (const float*)d_in[11];
    const float* b2       = (const float*)d_in[12];
    float* out = (float*)d_out;

    static bool attr_set = false;
    if (!attr_set) {
        cudaFuncSetAttribute(rec_kernel, cudaFuncAttributeMaxDynamicSharedMemorySize,
                             SM_FLOATS * 4);
        attr_set = true;
    }

    pre0f_kernel<<<(B_TOT * S_LEN) / 64, 256>>>(features, w_ih0, b_ih0, b_hh0);
    rec_kernel<<<(B_TOT + BT - 1) / BT, NT, SM_FLOATS * 4>>>(
        w_ih0, w_hh0, w_ih1, w_hh1, b_ih1, b_hh1, w1, b1, w2, b2, out);
}